// round 13
// baseline (speedup 1.0000x reference)
#include <cuda_runtime.h>
#include <cuda_fp16.h>

#define BB 2
#define FIN 128
#define NN 192
#define SS 192
#define HH 4
#define DD 64
#define CC 256          // H*D
#define NEG 0.2f
#define TOTF 73728.0f   // B*S*N
#define L2E 1.44269504088896f
#define CH 6            // n per attn block -> 32*4*2 = 256 blocks
#define TPA 576
#define EPH 97          // half2 pitch for slab rows (odd -> conflict-free)
#define PW 257          // W_lin smem row pitch (odd)

// k_attn smem word offsets
#define W_SLAB 0        // half2 [192 s][97 pairs]          18624
#define W_SSV  18624    // half2 [6 n][192 s]                1152
#define W_PART 19776    // 1152 multi-use
#define W_RDEN 20928    // rdh: half2[96] (48 words used)     192
#define W_APH  21120    // f32[192]                           192
#define W_SGS  21312    // f32[64]                             64
#define W_SL   21376    // uchar[6][192]                      288
#define W_SLOT 21664    // uchar[6][192]                      288
#define W_CNT  21952    // int cnt[6] + wcnt[36]               44
#define W_TOT  21996    // 87984 B -> 2 blocks/SM

// k_proj smem words
#define P_SU  16448
#define P_WAT 16960
#define P_DC  17088
#define P_TOT 17096     // 68384 B

__device__ __forceinline__ __half2 h2ex2(__half2 x) {
    unsigned r, xi = *reinterpret_cast<unsigned*>(&x);
    asm("ex2.approx.f16x2 %0, %1;" : "=r"(r) : "r"(xi));
    return *reinterpret_cast<__half2*>(&r);
}

// ---------------- scratch ----------------
__device__ float d_sumxp2[FIN][BB * NN];      // per-f per-(b,n) X partials
__device__ float d_sumx[BB * FIN];
__device__ float d_SsrcP[2][BB][HH][NN][SS];  // f-half partials, pre-scaled log2e
__device__ float d_SdstP[2][BB][HH][NN][SS];

// ---------------- K1: fused prep + projections + X row-sum partials ----------------
// grid (192, 2, BB), block 192 (thread = s, 1 n per block)
__global__ void __launch_bounds__(192) k_proj(const float* __restrict__ X,
                                              const float* __restrict__ W_lin,
                                              const float* __restrict__ b_lin,
                                              const float* __restrict__ W_attn,
                                              const float* __restrict__ b_attn) {
    extern __shared__ float sm[];
    float* wsm = sm;             // [64][257] W_lin slice (later sxp/sxq)
    float* su  = sm + P_SU;      // [2][4][64]
    float* wat = sm + P_WAT;     // 128
    float* dc  = sm + P_DC;      // 8

    int tid = threadIdx.x;
    int half = blockIdx.y, b = blockIdx.z, n = blockIdx.x;

    if (tid < 128) wat[tid] = W_attn[tid];
    {
        const float4* Wp = (const float4*)(W_lin + (size_t)half * 64 * CC);
        for (int i = tid; i < 4096; i += 192) {
            int row = i >> 6, c4 = (i & 63) * 4;
            float4 v = Wp[i];
            float* d = wsm + row * PW + c4;
            d[0] = v.x; d[1] = v.y; d[2] = v.z; d[3] = v.w;
        }
    }
    __syncthreads();
    for (int e = tid; e < 512; e += 192) {
        int t = e >> 8, r = e & 255, h = r >> 6, fl = r & 63;
        const float* wrow = wsm + fl * PW + h * 64;
        const float* wa = wat + t * 64;
        float acc = 0.f;
        #pragma unroll 16
        for (int d = 0; d < 64; d++) acc += wrow[d] * wa[d];
        su[e] = acc;
    }
    if (tid < 8) {
        int t = tid >> 2, h = tid & 3;
        const float* wa = wat + t * 64;
        float acc = 0.f;
        #pragma unroll 8
        for (int d = 0; d < 64; d++) acc += __ldg(b_lin + h * 64 + d) * wa[d];
        dc[tid] = acc;
    }
    __syncthreads();

    float* sxp = sm;            // [16][193]
    float* sxq = sm + 3088;     // 192
    int s = tid;
    float as[HH] = {0.f, 0.f, 0.f, 0.f};
    float ad[HH] = {0.f, 0.f, 0.f, 0.f};

    const float* Xp = X + (((size_t)b * FIN + half * 64) * NN + n) * SS + s;
    const size_t FST = (size_t)NN * SS;

    for (int c = 0; c < 4; c++) {
        float xv[16];
        #pragma unroll
        for (int k = 0; k < 16; k++) xv[k] = Xp[(c * 16 + k) * FST];
        #pragma unroll
        for (int k = 0; k < 16; k++) {
            float x = xv[k];
            #pragma unroll
            for (int h = 0; h < HH; h++) {
                as[h] += x * su[h * 64 + c * 16 + k];
                ad[h] += x * su[256 + h * 64 + c * 16 + k];
            }
        }
        #pragma unroll
        for (int k = 0; k < 16; k++) sxp[k * 193 + tid] = xv[k];
        __syncthreads();
        {
            int f = tid / 12, g = tid % 12;
            float a = 0.f;
            #pragma unroll
            for (int j = 0; j < 16; j++) a += sxp[f * 193 + g * 16 + j];
            sxq[f * 12 + g] = a;
        }
        __syncthreads();
        if (tid < 16) {
            float a = 0.f;
            #pragma unroll
            for (int j = 0; j < 12; j++) a += sxq[tid * 12 + j];
            d_sumxp2[half * 64 + c * 16 + tid][b * NN + n] = a;
        }
        __syncthreads();
    }

    float cb = b_attn[0];
    #pragma unroll
    for (int h = 0; h < HH; h++) {
        float cs = (half == 0) ? (dc[h] + cb) : 0.f;
        float cd = (half == 0) ? dc[4 + h] : 0.f;
        d_SsrcP[half][b][h][n][s] = (as[h] + cs) * L2E;
        d_SdstP[half][b][h][n][s] = (ad[h] + cd) * L2E;
    }
}

// ---------------- K2: tiny fold d_sumxp2 -> d_sumx ----------------
__global__ void k_fold() {
    int t = threadIdx.x;   // 256
    int b = t >> 7, f = t & 127;
    const float* p = &d_sumxp2[f][b * NN];
    float a = 0.f;
    #pragma unroll 16
    for (int j = 0; j < NN; j++) a += p[j];
    d_sumx[b * FIN + f] = a;
}

// ---------------- K3: fused attention + sum_g + output ----------------
// grid (32, HH, BB) = 256 blocks, block 576, 2 blocks/SM.
__global__ void __launch_bounds__(TPA, 2) k_attn(const int* __restrict__ A,
                                                 const float* __restrict__ W_lin,
                                                 const float* __restrict__ b_lin,
                                                 float* __restrict__ out) {
    extern __shared__ float smem[];
    __half*        slabh = (__half*)(smem + W_SLAB);   // [s][194 halves]
    __half2*       slab2 = (__half2*)(smem + W_SLAB);  // [s][EPH]
    __half2*       ssv2  = (__half2*)(smem + W_SSV);   // [6][192]
    float*         part  = smem + W_PART;
    float2*        part2 = (float2*)part;
    __half2*       rdh   = (__half2*)(smem + W_RDEN);  // [96]
    float*         aph   = smem + W_APH;
    float*         sgs   = smem + W_SGS;
    unsigned char* slist = (unsigned char*)(smem + W_SL);
    unsigned char* slot  = (unsigned char*)(smem + W_SLOT);
    int*           cnt   = (int*)(smem + W_CNT);
    int*           wcnt  = cnt + 6;

    int tid = threadIdx.x;
    int h = blockIdx.y, b = blockIdx.z;
    int nbase = blockIdx.x * CH;
    const __half2 neg2 = __float2half2_rn(NEG);
    const __half2 zeroh = __float2half2_rn(0.f);

    // ---- prologue A: slab, ssv, ballots, sum_g partials ----
    {
        const float4* p0 = (const float4*)&d_SdstP[0][b][h][0][0];
        const float4* p1 = (const float4*)&d_SdstP[1][b][h][0][0];
        #pragma unroll
        for (int i = tid; i < NN * SS / 4; i += TPA) {
            float4 v0 = p0[i], v1 = p1[i];
            int e = i * 4;
            int m = e / SS, s = e % SS;
            slabh[(s    ) * 194 + m] = __float2half(v0.x + v1.x);
            slabh[(s + 1) * 194 + m] = __float2half(v0.y + v1.y);
            slabh[(s + 2) * 194 + m] = __float2half(v0.z + v1.z);
            slabh[(s + 3) * 194 + m] = __float2half(v0.w + v1.w);
        }
    }
    #pragma unroll
    for (int i = tid; i < CH * SS; i += TPA) {
        int n = i / SS, s = i - n * SS;
        float v = d_SsrcP[0][b][h][nbase + n][s] + d_SsrcP[1][b][h][nbase + n][s];
        ssv2[i] = __float2half2_rn(v);
    }
    unsigned bals[CH];
    int mkbits = 0;
    if (tid < SS) {
        #pragma unroll
        for (int ni = 0; ni < CH; ni++) {
            int mk = (A[tid * NN + nbase + ni] != 0);
            unsigned bal = __ballot_sync(0xFFFFFFFFu, mk);
            bals[ni] = bal;
            mkbits |= mk << ni;
            if ((tid & 31) == 0) wcnt[ni * 6 + (tid >> 5)] = __popc(bal);
        }
    }
    if (tid >= 64) {  // sum_g partials
        int t = tid - 64, d = t >> 3, k = t & 7;
        float acc = 0.f;
        const float* wp = W_lin + h * 64 + d;
        #pragma unroll
        for (int f = k * 16; f < k * 16 + 16; f++)
            acc += (d_sumx[f] + d_sumx[FIN + f]) * wp[f * CC];
        part[t] = acc;
    }
    __syncthreads();

    // ---- prologue B: lists + counts + sgs ----
    if (tid < SS) {
        int w = tid >> 5, l = tid & 31;
        unsigned lmask = (1u << l) - 1u;
        #pragma unroll
        for (int ni = 0; ni < CH; ni++) {
            if ((mkbits >> ni) & 1) {
                int base = 0;
                #pragma unroll
                for (int q = 0; q < 5; q++) base += (q < w) ? wcnt[ni * 6 + q] : 0;
                int pos = base + __popc(bals[ni] & lmask);
                slist[ni * 192 + pos] = (unsigned char)tid;
                slot[ni * 192 + tid] = (unsigned char)pos;
            } else {
                slot[ni * 192 + tid] = 255;
            }
        }
    }
    if (tid >= 192 && tid < 192 + CH) {
        int ni = tid - 192;
        cnt[ni] = wcnt[ni * 6] + wcnt[ni * 6 + 1] + wcnt[ni * 6 + 2]
                + wcnt[ni * 6 + 3] + wcnt[ni * 6 + 4] + wcnt[ni * 6 + 5];
    }
    __syncthreads();
    if (tid >= 256 && tid < 320) {
        int d = tid - 256;
        float s = 0.f;
        #pragma unroll
        for (int k = 0; k < 8; k++) s += part[d * 8 + k];
        sgs[d] = s + TOTF * b_lin[h * 64 + d];
    }
    __syncthreads();

    int p1p = tid % 96, jj = tid / 96;     // pass1: m-pair, s-chunk (6)
    int sI = tid % 192, jj3 = tid / 192;   // pass2: slot, m-pair-chunk (3)
    size_t cb0 = (size_t)b * CC + h * 64;
    float4* outp = (float4*)out;

    for (int ni = 0; ni < CH; ni++) {
        int c = cnt[ni];
        const unsigned char* sl = slist + ni * 192;
        const __half2* svn = ssv2 + ni * SS;

        // pass 1: denom partials over compacted s
        {
            int i0 = (c * jj) / 6, i1 = (c * (jj + 1)) / 6;
            float a0 = 0.f, a1 = 0.f;
            for (int i = i0; i < i1; i++) {
                int s = sl[i];
                __half2 t = __hadd2(svn[s], slab2[s * EPH + p1p]);
                t = __hmax2(t, __hmul2(t, neg2));
                float2 ef = __half22float2(h2ex2(t));
                a0 += ef.x; a1 += ef.y;
            }
            part2[jj * 96 + p1p] = make_float2(a0, a1);
        }
        __syncthreads();
        if (tid < 96) {
            float dx = 0.f, dy = 0.f;
            #pragma unroll
            for (int q = 0; q < 6; q++) {
                float2 v = part2[q * 96 + tid];
                dx += v.x; dy += v.y;
            }
            float rx = dx > 0.f ? __fdividef(1.f, dx) : 0.f;
            float ry = dy > 0.f ? __fdividef(1.f, dy) : 0.f;
            rdh[tid] = __floats2half2_rn(rx, ry);
        }
        // overlap: write output of previous n
        if (ni > 0) {
            int nOut = nbase + ni - 1;
            #pragma unroll
            for (int idx = tid; idx < 64 * 48; idx += TPA) {
                int d = idx / 48, s4 = idx - d * 48;
                float g = sgs[d];
                float4 a = ((const float4*)aph)[s4];
                outp[((cb0 + d) * NN + nOut) * 48 + s4] =
                    make_float4(a.x * g, a.y * g, a.z * g, a.w * g);
            }
        }
        __syncthreads();

        // pass 2: slot-mapped, rdh half2 + HFMA2 flush-8
        if (sI < c) {
            int s = sl[sI];
            __half2 sv = svn[s];
            const __half2* row = slab2 + s * EPH;
            const __half2* rq = rdh + jj3 * 32;
            float a = 0.f;
            #pragma unroll
            for (int k = 0; k < 4; k++) {
                __half2 hacc = zeroh;
                #pragma unroll
                for (int j = 0; j < 8; j++) {
                    int q = k * 8 + j;
                    __half2 t = __hadd2(sv, row[jj3 * 32 + q]);
                    t = __hmax2(t, __hmul2(t, neg2));
                    hacc = __hfma2(h2ex2(t), rq[q], hacc);
                }
                float2 f2 = __half22float2(hacc);
                a += f2.x + f2.y;
            }
            part[jj3 * 192 + sI] = a;
        }
        __syncthreads();
        if (tid < SS) {
            int k = slot[ni * 192 + tid];
            aph[tid] = (k != 255)
                ? part[k] + part[192 + k] + part[384 + k] : 0.f;
        }
        __syncthreads();
    }
    // final output
    {
        int nOut = nbase + CH - 1;
        #pragma unroll
        for (int idx = tid; idx < 64 * 48; idx += TPA) {
            int d = idx / 48, s4 = idx - d * 48;
            float g = sgs[d];
            float4 a = ((const float4*)aph)[s4];
            outp[((cb0 + d) * NN + nOut) * 48 + s4] =
                make_float4(a.x * g, a.y * g, a.z * g, a.w * g);
        }
    }
}

extern "C" void kernel_launch(void* const* d_in, const int* in_sizes, int n_in,
                              void* d_out, int out_size) {
    const float* X      = (const float*)d_in[0];
    const int*   A      = (const int*)  d_in[1];
    const float* W_lin  = (const float*)d_in[2];
    const float* b_lin  = (const float*)d_in[3];
    const float* W_attn = (const float*)d_in[4];
    const float* b_attn = (const float*)d_in[5];
    float* out = (float*)d_out;

    const int SMEM_PROJ = P_TOT * 4;  // 68384 B
    const int SMEM_ATTN = W_TOT * 4;  // 87984 B
    cudaFuncSetAttribute(k_proj, cudaFuncAttributeMaxDynamicSharedMemorySize, SMEM_PROJ);
    cudaFuncSetAttribute(k_attn, cudaFuncAttributeMaxDynamicSharedMemorySize, SMEM_ATTN);

    k_proj<<<dim3(NN, 2, BB), 192, SMEM_PROJ>>>(X, W_lin, b_lin, W_attn, b_attn);
    k_fold<<<1, 256>>>();
    k_attn<<<dim3(NN / CH, HH, BB), TPA, SMEM_ATTN>>>(A, W_lin, b_lin, out);
}

// round 16
// speedup vs baseline: 1.3421x; 1.3421x over previous
#include <cuda_runtime.h>
#include <cuda_fp16.h>

#define BB 2
#define FIN 128
#define NN 192
#define SS 192
#define HH 4
#define DD 64
#define CC 256          // H*D
#define NEG 0.2f
#define TOTF 73728.0f   // B*S*N
#define L2E 1.44269504088896f
#define CH 6            // n per attn block -> 32*4*2 = 256 blocks
#define TPA 576
#define EPH 97          // half2 pitch for slab rows (odd -> conflict-free)
#define PW 257          // W_lin smem row pitch (odd)

// k_attn smem word offsets (round-8 layout)
#define W_SLAB 0        // half2 [192 s][97 pairs]          18624
#define W_SSV  18624    // half2 [6 n][192 s]                1152
#define W_PART 19776    // 1152 multi-use
#define W_RDEN 20928    // float2[96]                         192
#define W_APH  21120    // f32[192]                           192
#define W_SGS  21312    // f32[64]                             64
#define W_SL   21376    // uchar[6][192]                      288
#define W_SLOT 21664    // uchar[6][192]                      288
#define W_CNT  21952    // int cnt[6] + wcnt[36]               44
#define W_TOT  21996    // 87984 B -> 2 blocks/SM

// k_proj smem words
#define P_SU  16448
#define P_WAT 16960
#define P_DC  17088
#define P_TOT 17096     // 68384 B

__device__ __forceinline__ __half2 h2ex2(__half2 x) {
    unsigned r, xi = *reinterpret_cast<unsigned*>(&x);
    asm("ex2.approx.f16x2 %0, %1;" : "=r"(r) : "r"(xi));
    return *reinterpret_cast<__half2*>(&r);
}

// ---------------- scratch ----------------
__device__ float d_sumxp2[FIN][BB * 96];      // per-f per-(b,bx) X partials
__device__ float d_sumx[BB * FIN];
__device__ float d_SsrcP[2][BB][HH][NN][SS];  // f-half partials, pre-scaled log2e
__device__ float d_SdstP[2][BB][HH][NN][SS];

// ---------------- K1: fused prep + projections + X row-sum partials ----------------
// grid (96, 2, BB), block 192  (round-12 exact)
__global__ void __launch_bounds__(192) k_proj(const float* __restrict__ X,
                                              const float* __restrict__ W_lin,
                                              const float* __restrict__ b_lin,
                                              const float* __restrict__ W_attn,
                                              const float* __restrict__ b_attn) {
    extern __shared__ float sm[];
    float* wsm = sm;             // [64][257] W_lin slice (then sxp/sxq)
    float* su  = sm + P_SU;      // [2][4][64]
    float* wat = sm + P_WAT;     // 128
    float* dc  = sm + P_DC;      // 8

    int tid = threadIdx.x;
    int half = blockIdx.y, b = blockIdx.z, bx = blockIdx.x;

    if (tid < 128) wat[tid] = W_attn[tid];
    {
        const float4* Wp = (const float4*)(W_lin + (size_t)half * 64 * CC);
        for (int i = tid; i < 4096; i += 192) {
            int row = i >> 6, c4 = (i & 63) * 4;
            float4 v = Wp[i];
            float* d = wsm + row * PW + c4;
            d[0] = v.x; d[1] = v.y; d[2] = v.z; d[3] = v.w;
        }
    }
    __syncthreads();
    for (int e = tid; e < 512; e += 192) {
        int t = e >> 8, r = e & 255, h = r >> 6, fl = r & 63;
        const float* wrow = wsm + fl * PW + h * 64;
        const float* wa = wat + t * 64;
        float acc = 0.f;
        #pragma unroll 16
        for (int d = 0; d < 64; d++) acc += wrow[d] * wa[d];
        su[e] = acc;
    }
    if (tid < 8) {
        int t = tid >> 2, h = tid & 3;
        const float* wa = wat + t * 64;
        float acc = 0.f;
        #pragma unroll 8
        for (int d = 0; d < 64; d++) acc += __ldg(b_lin + h * 64 + d) * wa[d];
        dc[tid] = acc;
    }
    __syncthreads();

    float* sxp = sm;            // [16][193]
    float* sxq = sm + 3088;     // 192
    int s2 = tid % 96, nn = tid / 96;
    int n = bx * 2 + nn;
    float as[2][HH], ad[2][HH];
    #pragma unroll
    for (int j = 0; j < 2; j++)
        #pragma unroll
        for (int h = 0; h < HH; h++) { as[j][h] = 0.f; ad[j][h] = 0.f; }

    const float2* Xp = (const float2*)(X + (((size_t)b * FIN + half * 64) * NN + n) * SS) + s2;
    const size_t FST2 = (size_t)NN * SS / 2;

    for (int c = 0; c < 4; c++) {
        float2 xv[16];
        #pragma unroll
        for (int k = 0; k < 16; k++) xv[k] = Xp[(c * 16 + k) * FST2];
        #pragma unroll
        for (int k = 0; k < 16; k++) {
            #pragma unroll
            for (int h = 0; h < HH; h++) {
                float wu = su[h * 64 + c * 16 + k];
                float wd = su[256 + h * 64 + c * 16 + k];
                as[0][h] += xv[k].x * wu;  ad[0][h] += xv[k].x * wd;
                as[1][h] += xv[k].y * wu;  ad[1][h] += xv[k].y * wd;
            }
        }
        #pragma unroll
        for (int k = 0; k < 16; k++) sxp[k * 193 + tid] = xv[k].x + xv[k].y;
        __syncthreads();
        {
            int f = tid / 12, g = tid % 12;
            float a = 0.f;
            #pragma unroll
            for (int j = 0; j < 16; j++) a += sxp[f * 193 + g * 16 + j];
            sxq[f * 12 + g] = a;
        }
        __syncthreads();
        if (tid < 16) {
            float a = 0.f;
            #pragma unroll
            for (int j = 0; j < 12; j++) a += sxq[tid * 12 + j];
            d_sumxp2[half * 64 + c * 16 + tid][b * 96 + bx] = a;
        }
        __syncthreads();
    }

    float cb = b_attn[0];
    #pragma unroll
    for (int h = 0; h < HH; h++) {
        float cs = (half == 0) ? (dc[h] + cb) : 0.f;
        float cd = (half == 0) ? dc[4 + h] : 0.f;
        float2 vs = make_float2((as[0][h] + cs) * L2E, (as[1][h] + cs) * L2E);
        float2 vd = make_float2((ad[0][h] + cd) * L2E, (ad[1][h] + cd) * L2E);
        ((float2*)&d_SsrcP[half][b][h][n][0])[s2] = vs;
        ((float2*)&d_SdstP[half][b][h][n][0])[s2] = vd;
    }
}

// ---------------- K2: tiny fold d_sumxp2 -> d_sumx ----------------
__global__ void k_fold() {
    int t = threadIdx.x;   // 256
    int b = t >> 7, f = t & 127;
    const float* p = &d_sumxp2[f][b * 96];
    float a = 0.f;
    #pragma unroll 16
    for (int j = 0; j < 96; j++) a += p[j];
    d_sumx[b * FIN + f] = a;
}

// ---------------- K3: fused attention + sum_g + output (round-8 core, exact) ----------------
// grid (32, HH, BB) = 256 blocks, block 576, 2 blocks/SM.
__global__ void __launch_bounds__(TPA, 2) k_attn(const int* __restrict__ A,
                                                 const float* __restrict__ W_lin,
                                                 const float* __restrict__ b_lin,
                                                 float* __restrict__ out) {
    extern __shared__ float smem[];
    __half*        slabh = (__half*)(smem + W_SLAB);   // [s][194 halves]
    __half2*       slab2 = (__half2*)(smem + W_SLAB);  // [s][EPH]
    __half2*       ssv2  = (__half2*)(smem + W_SSV);   // [6][192]
    float*         part  = smem + W_PART;
    float2*        part2 = (float2*)part;
    float2*        rden2 = (float2*)(smem + W_RDEN);
    float*         aph   = smem + W_APH;
    float*         sgs   = smem + W_SGS;
    unsigned char* slist = (unsigned char*)(smem + W_SL);
    unsigned char* slot  = (unsigned char*)(smem + W_SLOT);
    int*           cnt   = (int*)(smem + W_CNT);
    int*           wcnt  = cnt + 6;

    int tid = threadIdx.x;
    int h = blockIdx.y, b = blockIdx.z;
    int nbase = blockIdx.x * CH;
    const __half2 neg2 = __float2half2_rn(NEG);

    // ---- prologue A: slab, ssv, ballots, sum_g partials ----
    {
        const float4* p0 = (const float4*)&d_SdstP[0][b][h][0][0];
        const float4* p1 = (const float4*)&d_SdstP[1][b][h][0][0];
        #pragma unroll
        for (int i = tid; i < NN * SS / 4; i += TPA) {
            float4 v0 = p0[i], v1 = p1[i];
            int e = i * 4;
            int m = e / SS, s = e % SS;
            slabh[(s    ) * 194 + m] = __float2half(v0.x + v1.x);
            slabh[(s + 1) * 194 + m] = __float2half(v0.y + v1.y);
            slabh[(s + 2) * 194 + m] = __float2half(v0.z + v1.z);
            slabh[(s + 3) * 194 + m] = __float2half(v0.w + v1.w);
        }
    }
    #pragma unroll
    for (int i = tid; i < CH * SS; i += TPA) {
        int n = i / SS, s = i - n * SS;
        float v = d_SsrcP[0][b][h][nbase + n][s] + d_SsrcP[1][b][h][nbase + n][s];
        ssv2[i] = __float2half2_rn(v);
    }
    unsigned bals[CH];
    int mkbits = 0;
    if (tid < SS) {
        #pragma unroll
        for (int ni = 0; ni < CH; ni++) {
            int mk = (A[tid * NN + nbase + ni] != 0);
            unsigned bal = __ballot_sync(0xFFFFFFFFu, mk);
            bals[ni] = bal;
            mkbits |= mk << ni;
            if ((tid & 31) == 0) wcnt[ni * 6 + (tid >> 5)] = __popc(bal);
        }
    }
    if (tid >= 64) {  // sum_g partials
        int t = tid - 64, d = t >> 3, k = t & 7;
        float acc = 0.f;
        const float* wp = W_lin + h * 64 + d;
        #pragma unroll
        for (int f = k * 16; f < k * 16 + 16; f++)
            acc += (d_sumx[f] + d_sumx[FIN + f]) * wp[f * CC];
        part[t] = acc;
    }
    __syncthreads();

    // ---- prologue B: lists + counts + sgs ----
    if (tid < SS) {
        int w = tid >> 5, l = tid & 31;
        unsigned lmask = (1u << l) - 1u;
        #pragma unroll
        for (int ni = 0; ni < CH; ni++) {
            if ((mkbits >> ni) & 1) {
                int base = 0;
                #pragma unroll
                for (int q = 0; q < 5; q++) base += (q < w) ? wcnt[ni * 6 + q] : 0;
                int pos = base + __popc(bals[ni] & lmask);
                slist[ni * 192 + pos] = (unsigned char)tid;
                slot[ni * 192 + tid] = (unsigned char)pos;
            } else {
                slot[ni * 192 + tid] = 255;
            }
        }
    }
    if (tid >= 192 && tid < 192 + CH) {
        int ni = tid - 192;
        cnt[ni] = wcnt[ni * 6] + wcnt[ni * 6 + 1] + wcnt[ni * 6 + 2]
                + wcnt[ni * 6 + 3] + wcnt[ni * 6 + 4] + wcnt[ni * 6 + 5];
    }
    __syncthreads();
    if (tid >= 256 && tid < 320) {
        int d = tid - 256;
        float s = 0.f;
        #pragma unroll
        for (int k = 0; k < 8; k++) s += part[d * 8 + k];
        sgs[d] = s + TOTF * b_lin[h * 64 + d];
    }
    __syncthreads();

    int p1p = tid % 96, jj = tid / 96;     // pass1: m-pair, s-chunk (6)
    int sI = tid % 192, jj3 = tid / 192;   // pass2: slot, m-pair-chunk (3)
    size_t cb0 = (size_t)b * CC + h * 64;
    float4* outp = (float4*)out;

    for (int ni = 0; ni < CH; ni++) {
        int c = cnt[ni];
        const unsigned char* sl = slist + ni * 192;
        const __half2* svn = ssv2 + ni * SS;

        // pass 1: denom partials over compacted s
        {
            int i0 = (c * jj) / 6, i1 = (c * (jj + 1)) / 6;
            float a0 = 0.f, a1 = 0.f;
            for (int i = i0; i < i1; i++) {
                int s = sl[i];
                __half2 t = __hadd2(svn[s], slab2[s * EPH + p1p]);
                t = __hmax2(t, __hmul2(t, neg2));
                float2 ef = __half22float2(h2ex2(t));
                a0 += ef.x; a1 += ef.y;
            }
            part2[jj * 96 + p1p] = make_float2(a0, a1);
        }
        __syncthreads();
        if (tid < 96) {
            float dx = 0.f, dy = 0.f;
            #pragma unroll
            for (int q = 0; q < 6; q++) {
                float2 v = part2[q * 96 + tid];
                dx += v.x; dy += v.y;
            }
            rden2[tid] = make_float2(dx > 0.f ? __fdividef(1.f, dx) : 0.f,
                                     dy > 0.f ? __fdividef(1.f, dy) : 0.f);
        }
        // overlap: write output of previous n
        if (ni > 0) {
            int nOut = nbase + ni - 1;
            #pragma unroll
            for (int idx = tid; idx < 64 * 48; idx += TPA) {
                int d = idx / 48, s4 = idx - d * 48;
                float g = sgs[d];
                float4 a = ((const float4*)aph)[s4];
                outp[((cb0 + d) * NN + nOut) * 48 + s4] =
                    make_float4(a.x * g, a.y * g, a.z * g, a.w * g);
            }
        }
        __syncthreads();

        // pass 2: alpha partials (round-8 exact, fp32 rden2)
        if (sI < c) {
            int s = sl[sI];
            __half2 sv = svn[s];
            const __half2* row = slab2 + s * EPH;
            float a = 0.f;
            #pragma unroll 4
            for (int q = jj3 * 32; q < jj3 * 32 + 32; q++) {
                __half2 t = __hadd2(sv, row[q]);
                t = __hmax2(t, __hmul2(t, neg2));
                float2 ef = __half22float2(h2ex2(t));
                float2 r = rden2[q];
                a += ef.x * r.x + ef.y * r.y;
            }
            part[jj3 * 192 + sI] = a;
        }
        __syncthreads();
        if (tid < SS) {
            int k = slot[ni * 192 + tid];
            aph[tid] = (k != 255)
                ? part[k] + part[192 + k] + part[384 + k] : 0.f;
        }
        __syncthreads();
    }
    // final output
    {
        int nOut = nbase + CH - 1;
        #pragma unroll
        for (int idx = tid; idx < 64 * 48; idx += TPA) {
            int d = idx / 48, s4 = idx - d * 48;
            float g = sgs[d];
            float4 a = ((const float4*)aph)[s4];
            outp[((cb0 + d) * NN + nOut) * 48 + s4] =
                make_float4(a.x * g, a.y * g, a.z * g, a.w * g);
        }
    }
}

extern "C" void kernel_launch(void* const* d_in, const int* in_sizes, int n_in,
                              void* d_out, int out_size) {
    const float* X      = (const float*)d_in[0];
    const int*   A      = (const int*)  d_in[1];
    const float* W_lin  = (const float*)d_in[2];
    const float* b_lin  = (const float*)d_in[3];
    const float* W_attn = (const float*)d_in[4];
    const float* b_attn = (const float*)d_in[5];
    float* out = (float*)d_out;

    const int SMEM_PROJ = P_TOT * 4;  // 68384 B
    const int SMEM_ATTN = W_TOT * 4;  // 87984 B
    cudaFuncSetAttribute(k_proj, cudaFuncAttributeMaxDynamicSharedMemorySize, SMEM_PROJ);
    cudaFuncSetAttribute(k_attn, cudaFuncAttributeMaxDynamicSharedMemorySize, SMEM_ATTN);

    k_proj<<<dim3(96, 2, BB), 192, SMEM_PROJ>>>(X, W_lin, b_lin, W_attn, b_attn);
    k_fold<<<1, 256>>>();
    k_attn<<<dim3(NN / CH, HH, BB), TPA, SMEM_ATTN>>>(A, W_lin, b_lin, out);
}